// round 14
// baseline (speedup 1.0000x reference)
#include <cuda_runtime.h>
#include <cuda_bf16.h>
#include <cuda_fp16.h>
#include <stdint.h>
#include <math.h>

#define NB  4
#define TW  1024
#define TE  128
#define TT  1152
#define HD  1024
#define NHD 16
#define DHD 64

#define SX_Q 24.0f
#define SW_Q 1280.0f
#define INVS (1.0f/(24.0f*1280.0f))

// ---------------- scratch ----------------
__device__ float  g_Y [(NB*TW + NB*TE)*HD];   // unified pre-LN temp
__device__ __half g_QH[NB*NHD*TT*DHD];        // fp16 head-layout Q (pre-scaled 0.125*log2e)
__device__ __half g_KH[NB*NHD*TT*DHD];
__device__ __half g_VH[NB*NHD*TT*DHD];
__device__ __half g_Xh[4608*1024];            // CTX fp16 (attention output -> out-proj input)
__device__ int8_t g_Xq[5120*1024];            // int8 activations (scale SX_Q)
__device__ int8_t g_W8[6*1024*1024];          // int8 QKV weights, transposed [N,K] (scale SW_Q)
__device__ __half g_Wt[2*1024*1024];          // fp16 Wo, Weo transposed

// ---------------- helpers ----------------
__device__ __forceinline__ uint32_t smem_u32(const void* p){
    uint32_t a;
    asm("{ .reg .u64 t; cvta.to.shared.u64 t, %1; cvt.u32.u64 %0, t; }" : "=r"(a) : "l"(p));
    return a;
}
__device__ __forceinline__ uint32_t pkh(float a, float b){
    __half2 h = __floats2half2_rn(a, b);
    return *reinterpret_cast<uint32_t*>(&h);
}
__device__ __forceinline__ uint32_t ex2h2(uint32_t x){
    uint32_t r; asm("ex2.approx.f16x2 %0, %1;" : "=r"(r) : "r"(x)); return r;
}
__device__ __forceinline__ uint32_t hadd2u(uint32_t a, uint32_t b){
    uint32_t r; asm("add.f16x2 %0, %1, %2;" : "=r"(r) : "r"(a), "r"(b)); return r;
}
__device__ __forceinline__ float h2sumf(uint32_t h){
    __half2 v = *reinterpret_cast<__half2*>(&h);
    float2 f = __half22float2(v);
    return f.x + f.y;
}
__device__ __forceinline__ int q8(float v, float s){
    float f = fminf(fmaxf(v * s, -127.f), 127.f);
    return __float2int_rn(f);
}
__device__ __forceinline__ uint32_t pk4(int a, int b, int c, int d){
    return (uint32_t)(a & 255) | ((uint32_t)(b & 255) << 8) |
           ((uint32_t)(c & 255) << 16) | ((uint32_t)(d & 255) << 24);
}

#define CPA16(dst, src) asm volatile("cp.async.cg.shared.global [%0], [%1], 16;" :: "r"(dst), "l"(src))
#define CPA_COMMIT()    asm volatile("cp.async.commit_group;" ::: "memory")
template<int N> __device__ __forceinline__ void cpa_wait(){
    asm volatile("cp.async.wait_group %0;" :: "n"(N) : "memory");
}

__device__ __forceinline__ void ldsm4(uint32_t* r, uint32_t addr){
    asm volatile("ldmatrix.sync.aligned.m8n8.x4.shared.b16 {%0,%1,%2,%3}, [%4];"
        : "=r"(r[0]), "=r"(r[1]), "=r"(r[2]), "=r"(r[3]) : "r"(addr));
}
__device__ __forceinline__ void ldsm4t(uint32_t* r, uint32_t addr){
    asm volatile("ldmatrix.sync.aligned.m8n8.x4.trans.shared.b16 {%0,%1,%2,%3}, [%4];"
        : "=r"(r[0]), "=r"(r[1]), "=r"(r[2]), "=r"(r[3]) : "r"(addr));
}
__device__ __forceinline__ void mma16816h(float* d, const uint32_t* a, const uint32_t* b){
    asm volatile("mma.sync.aligned.m16n8k16.row.col.f32.f16.f16.f32 "
        "{%0,%1,%2,%3}, {%4,%5,%6,%7}, {%8,%9}, {%0,%1,%2,%3};"
        : "+f"(d[0]), "+f"(d[1]), "+f"(d[2]), "+f"(d[3])
        : "r"(a[0]), "r"(a[1]), "r"(a[2]), "r"(a[3]), "r"(b[0]), "r"(b[1]));
}
__device__ __forceinline__ void imma16832(int* d, const uint32_t* a, const uint32_t* b){
    asm volatile("mma.sync.aligned.m16n8k32.row.col.s32.s8.s8.s32 "
        "{%0,%1,%2,%3}, {%4,%5,%6,%7}, {%8,%9}, {%0,%1,%2,%3};"
        : "+r"(d[0]), "+r"(d[1]), "+r"(d[2]), "+r"(d[3])
        : "r"(a[0]), "r"(a[1]), "r"(a[2]), "r"(a[3]), "r"(b[0]), "r"(b[1]));
}

// ---------------- unified prep ----------------
// z 0..5: int8 QKV weights; z 6..7: fp16 Wo/Weo; z 8: int8 activations
struct PrepArgs {
    const float* w[8];
    const float* word; const float* ent; const float* qp;
};

__global__ __launch_bounds__(256) void prep_kernel(PrepArgs pa, int8_t* W8, __half* Wt, int8_t* Xq){
    __shared__ float tile[32][33];
    const int z = blockIdx.z;
    if (z < 8) {
        if (blockIdx.x >= 1024) return;
        const float* W = pa.w[z];
        int n0 = (blockIdx.x & 31) * 32, k0 = (blockIdx.x >> 5) * 32;
        int tx = threadIdx.x & 31, ty = threadIdx.x >> 5;
        #pragma unroll
        for (int i = 0; i < 32; i += 8)
            tile[ty + i][tx] = W[(size_t)(k0 + ty + i) * 1024 + n0 + tx];
        __syncthreads();
        if (z < 6) {
            #pragma unroll
            for (int i = 0; i < 32; i += 8) {
                float f = tile[tx][ty + i];
                size_t o = ((size_t)z << 20) + ((size_t)(n0 + ty + i) << 10) + k0 + tx;
                W8[o] = (int8_t)q8(f, SW_Q);
            }
        } else {
            #pragma unroll
            for (int i = 0; i < 32; i += 8) {
                float f = tile[tx][ty + i];
                size_t o = ((size_t)(z - 6) << 20) + ((size_t)(n0 + ty + i) << 10) + k0 + tx;
                Wt[o] = __float2half_rn(f);
            }
        }
    } else {
        size_t base4 = (size_t)blockIdx.x * 1024;
        #pragma unroll
        for (int i = 0; i < 4; i++) {
            size_t idx4 = base4 + threadIdx.x + i * 256;
            size_t row = idx4 >> 8;
            float4 v;
            if (row < 4096) {
                v = ((const float4*)pa.word)[idx4];
            } else if (row < 4608) {
                size_t off = idx4 - (size_t)4096 * 256;
                float4 a = ((const float4*)pa.ent)[off];
                float4 b = ((const float4*)pa.qp)[off];
                v = make_float4((a.x+b.x)*0.5f,(a.y+b.y)*0.5f,(a.z+b.z)*0.5f,(a.w+b.w)*0.5f);
            } else {
                size_t off = idx4 - (size_t)4608 * 256;
                v = ((const float4*)pa.ent)[off];
            }
            ((uint32_t*)Xq)[idx4] = pk4(q8(v.x, SX_Q), q8(v.y, SX_Q), q8(v.z, SX_Q), q8(v.w, SX_Q));
        }
    }
}

// ---------------- shared tile geometry ----------------
#define STRB  144
#define OFF_B 18432
#define BUFSZ 36864
#define SMEM_GEMM (2*BUFSZ)
#define L2E 1.44269504f

struct GemmCfg {
    const float* bias0[3]; const float* bias1[3];
    void* o[3];
    const float* res0; const float* res1;
    int widx0, widx1;
    int mode;
    int ySplit;
    int Tseg0, Tfull0, toff0, toffOut0, xb01_0, xb2_0;
    int Tseg1, Tfull1, toff1, toffOut1, xb01_1, xb2_1;
    int outRowBase1;
};

// ---------------- int8 IMMA GEMM: QKV projections (scatter fp16 head layout) ----------------
__global__ __launch_bounds__(256, 2) void gemm_i8(
    const int8_t* __restrict__ Xq, const int8_t* __restrict__ W8all, GemmCfg cfg)
{
    extern __shared__ char smc[];
    const uint32_t sb = smem_u32(smc);
    const int tid = threadIdx.x;
    const int wid = tid >> 5, lane = tid & 31;
    const int wm = wid >> 1, wn = wid & 1;
    const int z = blockIdx.z;

    const int seg = (blockIdx.y >= cfg.ySplit) ? 1 : 0;
    const int yy  = seg ? blockIdx.y - cfg.ySplit : blockIdx.y;

    const float* bias = (seg ? cfg.bias1 : cfg.bias0)[z];
    __half* out = (__half*)cfg.o[z];
    const int Tseg    = seg ? cfg.Tseg1    : cfg.Tseg0;
    const int toffOut = seg ? cfg.toffOut1 : cfg.toffOut0;
    const int xb      = (z == 2) ? (seg ? cfg.xb2_1 : cfg.xb2_0)
                                 : (seg ? cfg.xb01_1 : cfg.xb01_0);
    const int widx    = (seg ? cfg.widx1 : cfg.widx0) + z;

    const int8_t* W8 = W8all + ((size_t)widx << 20);
    const float oscale = (z == 0) ? (0.125f * L2E * INVS) : INVS;

    const int m0 = yy * 128;
    const int n0 = blockIdx.x * 128;
    const int b2 = m0 / Tseg;
    const int t0 = m0 - b2 * Tseg;
    const int8_t* Ah = Xq + ((size_t)(xb + m0)) * HD;

    int acc[2][8][4];
    #pragma unroll
    for (int mt = 0; mt < 2; mt++)
        #pragma unroll
        for (int nt = 0; nt < 8; nt++)
            #pragma unroll
            for (int j = 0; j < 4; j++) acc[mt][nt][j] = 0;

    auto issue_chunk = [&](int ch, int buf){
        const int k0 = ch * 128;
        const uint32_t base = sb + buf * BUFSZ;
        #pragma unroll
        for (int i = 0; i < 4; i++) {
            int q = tid + i * 256;
            int r = q >> 3, s8 = q & 7;
            CPA16(base + r * STRB + s8 * 16,         Ah + (size_t)r * HD + k0 + s8 * 16);
            CPA16(base + OFF_B + r * STRB + s8 * 16, W8 + (size_t)(n0 + r) * HD + k0 + s8 * 16);
        }
    };

    issue_chunk(0, 0);
    CPA_COMMIT();

    const int arow = (lane & 7) + ((lane >> 3) & 1) * 8;
    const int acol8 = (lane >> 4) * 8;
    const int bnof = (lane & 7) + ((lane >> 4) << 3);
    const int bk8  = ((lane >> 3) & 1) * 8;

    int buf = 0;
    for (int ch = 0; ch < 8; ch++) {
        if (ch < 7) { issue_chunk(ch + 1, buf ^ 1); CPA_COMMIT(); cpa_wait<1>(); }
        else        { cpa_wait<0>(); }
        __syncthreads();

        const uint32_t base = sb + buf * BUFSZ;
        #pragma unroll
        for (int ks = 0; ks < 4; ks++) {
            uint32_t aF[2][4];
            #pragma unroll
            for (int mt = 0; mt < 2; mt++)
                ldsm4(aF[mt], base + (wm*32 + mt*16 + arow) * STRB + (ks*16 + acol8) * 2);
            uint32_t bF[4][4];
            #pragma unroll
            for (int np = 0; np < 4; np++)
                ldsm4(bF[np], base + OFF_B + (wn*64 + np*16 + bnof) * STRB + (ks*16 + bk8) * 2);
            #pragma unroll
            for (int mt = 0; mt < 2; mt++)
                #pragma unroll
                for (int nt = 0; nt < 8; nt++)
                    imma16832(acc[mt][nt], aF[mt], &bF[nt >> 1][(nt & 1) * 2]);
        }
        __syncthreads();
        buf ^= 1;
    }

    #pragma unroll
    for (int mt = 0; mt < 2; mt++) {
        #pragma unroll
        for (int hf = 0; hf < 2; hf++) {
            int lr = wm*32 + mt*16 + (lane >> 2) + hf*8;
            int t2 = t0 + lr;
            #pragma unroll
            for (int nt = 0; nt < 8; nt++) {
                int c = n0 + wn*64 + nt*8 + (lane & 3)*2;
                float v0 = ((float)acc[mt][nt][hf*2+0]) * INVS + __ldg(bias + c);
                float v1 = ((float)acc[mt][nt][hf*2+1]) * INVS + __ldg(bias + c + 1);
                float sc = (z == 0) ? (0.125f * L2E) : 1.f;
                int h = c >> 6, d = c & 63;
                size_t o = (((size_t)(b2*NHD + h) * TT + toffOut + t2) << 6) + d;
                *(uint32_t*)(out + o) = pkh(v0 * sc, v1 * sc);
            }
        }
    }
    (void)oscale;
}

// ---------------- fp16 HMMA GEMM: out-projections (mode 1) ----------------
__global__ __launch_bounds__(256, 2) void gemm_mma(
    const __half* __restrict__ Xh, const __half* __restrict__ WtAll, GemmCfg cfg)
{
    extern __shared__ char smc[];
    const uint32_t sb = smem_u32(smc);
    const int tid = threadIdx.x;
    const int wid = tid >> 5, lane = tid & 31;
    const int wm = wid >> 1, wn = wid & 1;

    const int seg = (blockIdx.y >= cfg.ySplit) ? 1 : 0;
    const int yy  = seg ? blockIdx.y - cfg.ySplit : blockIdx.y;

    const float* bias = (seg ? cfg.bias1 : cfg.bias0)[0];
    float* out = (float*)cfg.o[0];
    const int Tseg  = seg ? cfg.Tseg1  : cfg.Tseg0;
    const int Tfull = seg ? cfg.Tfull1 : cfg.Tfull0;
    const int toff  = seg ? cfg.toff1  : cfg.toff0;
    const float* res  = seg ? cfg.res1 : cfg.res0;
    const int widx    = seg ? cfg.widx1 : cfg.widx0;
    const int outBase = seg ? cfg.outRowBase1 : 0;

    const __half* Wt = WtAll + ((size_t)widx << 20);

    const int m0 = yy * 128;
    const int n0 = blockIdx.x * 128;
    const int b2 = m0 / Tseg;
    const int t0 = m0 - b2 * Tseg;
    const __half* Ah = Xh + ((size_t)(b2 * Tfull + toff + t0)) * HD;

    float acc[2][8][4];
    #pragma unroll
    for (int mt = 0; mt < 2; mt++)
        #pragma unroll
        for (int nt = 0; nt < 8; nt++)
            #pragma unroll
            for (int j = 0; j < 4; j++) acc[mt][nt][j] = 0.f;

    auto issue_chunk = [&](int ch, int buf){
        const int k0 = ch * 64;
        const uint32_t base = sb + buf * BUFSZ;
        #pragma unroll
        for (int i = 0; i < 4; i++) {
            int q = tid + i * 256;
            int r = q >> 3, s8 = q & 7;
            CPA16(base + r * STRB + s8 * 16,         Ah + (size_t)r * HD + k0 + s8 * 8);
            CPA16(base + OFF_B + r * STRB + s8 * 16, Wt + (size_t)(n0 + r) * HD + k0 + s8 * 8);
        }
    };

    issue_chunk(0, 0);
    CPA_COMMIT();

    const int arow = (lane & 7) + ((lane >> 3) & 1) * 8;
    const int acol8 = (lane >> 4) * 8;
    const int bnof = (lane & 7) + ((lane >> 4) << 3);
    const int bk8  = ((lane >> 3) & 1) * 8;

    int buf = 0;
    for (int ch = 0; ch < 16; ch++) {
        if (ch < 15) { issue_chunk(ch + 1, buf ^ 1); CPA_COMMIT(); cpa_wait<1>(); }
        else         { cpa_wait<0>(); }
        __syncthreads();

        const uint32_t base = sb + buf * BUFSZ;
        #pragma unroll
        for (int ks = 0; ks < 4; ks++) {
            uint32_t aF[2][4];
            #pragma unroll
            for (int mt = 0; mt < 2; mt++)
                ldsm4(aF[mt], base + (wm*32 + mt*16 + arow) * STRB + (ks*16 + acol8) * 2);
            uint32_t bF[4][4];
            #pragma unroll
            for (int np = 0; np < 4; np++)
                ldsm4(bF[np], base + OFF_B + (wn*64 + np*16 + bnof) * STRB + (ks*16 + bk8) * 2);
            #pragma unroll
            for (int mt = 0; mt < 2; mt++)
                #pragma unroll
                for (int nt = 0; nt < 8; nt++)
                    mma16816h(acc[mt][nt], aF[mt], &bF[nt >> 1][(nt & 1) * 2]);
        }
        __syncthreads();
        buf ^= 1;
    }

    #pragma unroll
    for (int mt = 0; mt < 2; mt++) {
        #pragma unroll
        for (int hf = 0; hf < 2; hf++) {
            int lr = wm*32 + mt*16 + (lane >> 2) + hf*8;
            #pragma unroll
            for (int nt = 0; nt < 8; nt++) {
                int c = n0 + wn*64 + nt*8 + (lane & 3)*2;
                float v0 = acc[mt][nt][hf*2+0] + __ldg(bias + c);
                float v1 = acc[mt][nt][hf*2+1] + __ldg(bias + c + 1);
                size_t ro = (size_t)(m0 + lr) * HD + c;
                float2 rr = *(const float2*)(res + ro);
                size_t oo = (size_t)(outBase + m0 + lr) * HD + c;
                *(float2*)(out + oo) = make_float2(v0 + rr.x, v1 + rr.y);
            }
        }
    }
}

// ---------------- fp16 flash attention (round-13 best) ----------------
#define AO_KF 18432
#define AO_VF 55296
#define AO_MK 92160
#define ATTN_SMEM 96768

__global__ __launch_bounds__(256, 2) void attn_tc(
    const __half* __restrict__ Q, const __half* __restrict__ K,
    const __half* __restrict__ V, const float* __restrict__ mask,
    __half* __restrict__ OutH)
{
    extern __shared__ char smc[];
    const uint32_t sbase = smem_u32(smc);
    float* mks = (float*)(smc + AO_MK);

    const int tid = threadIdx.x, wid = tid >> 5, lane = tid & 31;
    const int bh = blockIdx.y, b = bh >> 4, h = bh & 15;
    const int q0 = blockIdx.x * 128;
    const __half* Qg = Q + ((size_t)bh * TT + q0) * DHD;
    const __half* Kg = K + (size_t)bh * TT * DHD;
    const __half* Vg = V + (size_t)bh * TT * DHD;
    const float* mb = mask + (size_t)b * TT;

    auto loadQ = [&](){
        #pragma unroll
        for (int i = 0; i < 4; i++) {
            int q = tid + i * 256;
            int r = q >> 3, s = q & 7;
            CPA16(sbase + r * STRB + s * 16, Qg + (size_t)r * DHD + s * 8);
        }
    };
    auto issueKV = [&](int ch, int buf){
        const __half* ks = Kg + (size_t)ch * 128 * DHD;
        const __half* vs = Vg + (size_t)ch * 128 * DHD;
        uint32_t kd = sbase + AO_KF + buf * 18432;
        uint32_t vd = sbase + AO_VF + buf * 18432;
        #pragma unroll
        for (int i = 0; i < 4; i++) {
            int q = tid + i * 256;
            int r = q >> 3, s = q & 7;
            CPA16(kd + r * STRB + s * 16, ks + (size_t)r * DHD + s * 8);
            CPA16(vd + r * STRB + s * 16, vs + (size_t)r * DHD + s * 8);
        }
        CPA_COMMIT();
    };

    loadQ();
    issueKV(0, 0);

    #pragma unroll
    for (int i = 0; i < 5; i++) {
        int idx = tid + i * 256;
        if (idx < TT) mks[idx] = __ldg(mb + idx) * L2E;
    }

    const int r4 = lane >> 2, c4 = lane & 3;
    const int row0 = wid * 16 + r4;
    const int arow16 = lane & 15, acol8 = (lane >> 4) * 8;
    const int bnof = (lane & 7) + ((lane >> 4) << 3);
    const int bk8  = ((lane >> 3) & 1) * 8;
    const int vgrp = lane >> 3, vwi = lane & 7;

    float O[8][4];
    #pragma unroll
    for (int nt = 0; nt < 8; nt++)
        #pragma unroll
        for (int j = 0; j < 4; j++) O[nt][j] = 0.f;
    float m0 = -1e30f, m1 = -1e30f, l0 = 0.f, l1 = 0.f;

    int buf = 0;
    for (int ch = 0; ch < 9; ch++) {
        if (ch > 0) __syncthreads();
        if (ch < 8) { issueKV(ch + 1, buf ^ 1); cpa_wait<1>(); }
        else        { cpa_wait<0>(); }
        __syncthreads();

        const uint32_t kb = sbase + AO_KF + buf * 18432;
        const uint32_t vb = sbase + AO_VF + buf * 18432;

        float S[16][4];
        #pragma unroll
        for (int nt = 0; nt < 16; nt++)
            #pragma unroll
            for (int j = 0; j < 4; j++) S[nt][j] = 0.f;

        {
            uint32_t aQ[4][4];
            #pragma unroll
            for (int ks = 0; ks < 4; ks++)
                ldsm4(aQ[ks], sbase + (wid*16 + arow16) * STRB + (ks*16 + acol8) * 2);
            #pragma unroll
            for (int ntp = 0; ntp < 8; ntp++) {
                #pragma unroll
                for (int ks = 0; ks < 4; ks++) {
                    uint32_t bF[4];
                    ldsm4(bF, kb + (ntp*16 + bnof) * STRB + (ks*16 + bk8) * 2);
                    mma16816h(S[2*ntp],     aQ[ks], &bF[0]);
                    mma16816h(S[2*ntp + 1], aQ[ks], &bF[2]);
                }
            }
        }

        const int kgl = ch * 128;
        float mt0 = -1e30f, mt1 = -1e30f;
        #pragma unroll
        for (int nt = 0; nt < 16; nt++) {
            float mkx = mks[kgl + nt*8 + 2*c4];
            float mky = mks[kgl + nt*8 + 2*c4 + 1];
            S[nt][0] += mkx;
            S[nt][1] += mky;
            S[nt][2] += mkx;
            S[nt][3] += mky;
            mt0 = fmaxf(mt0, fmaxf(S[nt][0], S[nt][1]));
            mt1 = fmaxf(mt1, fmaxf(S[nt][2], S[nt][3]));
        }
        mt0 = fmaxf(mt0, __shfl_xor_sync(0xffffffffu, mt0, 1));
        mt0 = fmaxf(mt0, __shfl_xor_sync(0xffffffffu, mt0, 2));
        mt1 = fmaxf(mt1, __shfl_xor_sync(0xffffffffu, mt1, 1));
        mt1 = fmaxf(mt1, __shfl_xor_sync(0xffffffffu, mt1, 2));

        float mn0 = fmaxf(m0, mt0), mn1 = fmaxf(m1, mt1);
        float al0 = exp2f(m0 - mn0), al1 = exp2f(m1 - mn1);
        #pragma unroll
        for (int nt = 0; nt < 8; nt++) {
            O[nt][0] *= al0; O[nt][1] *= al0;
            O[nt][2] *= al1; O[nt][3] *= al1;
        }

        uint32_t la0 = 0u, lb0 = 0u, la1 = 0u, lb1 = 0u;
        #pragma unroll
        for (int t = 0; t < 8; t++) {
            uint32_t P[4];
            P[0] = ex2h2(pkh(S[2*t][0]   - mn0, S[2*t][1]   - mn0));
            P[1] = ex2h2(pkh(S[2*t][2]   - mn1, S[2*t][3]   - mn1));
            P[2] = ex2h2(pkh(S[2*t+1][0] - mn0, S[2*t+1][1] - mn0));
            P[3] = ex2h2(pkh(S[2*t+1][2] - mn1, S[2*t+1][3] - mn1));
            uint32_t p02 = hadd2u(P[0], P[2]);
            uint32_t p13 = hadd2u(P[1], P[3]);
            if (t & 1) { lb0 = hadd2u(lb0, p02); lb1 = hadd2u(lb1, p13); }
            else       { la0 = hadd2u(la0, p02); la1 = hadd2u(la1, p13); }
            #pragma unroll
            for (int dp = 0; dp < 4; dp++) {
                uint32_t bF[4];
                ldsm4t(bF, vb + (t*16 + (vgrp & 1)*8 + vwi) * STRB + (dp*16 + (vgrp >> 1)*8) * 2);
                mma16816h(O[2*dp],     P, &bF[0]);
                mma16816h(O[2*dp + 1], P, &bF[2]);
            }
        }
        {
            float ls0 = h2sumf(hadd2u(la0, lb0));
            float ls1 = h2sumf(hadd2u(la1, lb1));
            ls0 += __shfl_xor_sync(0xffffffffu, ls0, 1);
            ls0 += __shfl_xor_sync(0xffffffffu, ls0, 2);
            ls1 += __shfl_xor_sync(0xffffffffu, ls1, 1);
            ls1 += __shfl_xor_sync(0xffffffffu, ls1, 2);
            l0 = l0 * al0 + ls0; m0 = mn0;
            l1 = l1 * al1 + ls1; m1 = mn1;
        }
        buf ^= 1;
    }

    float i0 = 1.f / l0, i1 = 1.f / l1;
    #pragma unroll
    for (int nt = 0; nt < 8; nt++) {
        int c = h * 64 + nt*8 + 2*c4;
        size_t o0 = (size_t)(b * TT + q0 + row0) * HD + c;
        size_t o1 = (size_t)(b * TT + q0 + row0 + 8) * HD + c;
        *(uint32_t*)(OutH + o0) = pkh(O[nt][0] * i0, O[nt][1] * i0);
        *(uint32_t*)(OutH + o1) = pkh(O[nt][2] * i1, O[nt][3] * i1);
    }
}

// ---------------- layernorm ----------------
__device__ __forceinline__ float block_sum(float v, float* sh) {
    #pragma unroll
    for (int o = 16; o; o >>= 1) v += __shfl_xor_sync(0xffffffffu, v, o);
    int tid = threadIdx.x;
    if ((tid & 31) == 0) sh[tid >> 5] = v;
    __syncthreads();
    if (tid < 32) {
        float t = (tid < 8) ? sh[tid] : 0.f;
        #pragma unroll
        for (int o = 4; o; o >>= 1) t += __shfl_xor_sync(0xffffffffu, t, o);
        if (tid == 0) sh[0] = t;
    }
    __syncthreads();
    float r = sh[0];
    __syncthreads();
    return r;
}

__global__ __launch_bounds__(256) void ln_kernel(
    const float* __restrict__ Y,
    const float* __restrict__ g0, const float* __restrict__ b0,
    const float* __restrict__ g1, const float* __restrict__ b1,
    float* __restrict__ out)
{
    __shared__ float sh[8];
    int row = blockIdx.x, tid = threadIdx.x;
    const float* g  = (row < NB*TW) ? g0 : g1;
    const float* bt = (row < NB*TW) ? b0 : b1;
    float4 v = ((const float4*)(Y + (size_t)row * HD))[tid];
    float mu = block_sum(v.x + v.y + v.z + v.w, sh) * (1.f / HD);
    float4 d = make_float4(v.x - mu, v.y - mu, v.z - mu, v.w - mu);
    float var = block_sum(d.x*d.x + d.y*d.y + d.z*d.z + d.w*d.w, sh) * (1.f / HD);
    float rs = rsqrtf(var + 1e-12f);
    float4 gg = ((const float4*)g)[tid];
    float4 bb = ((const float4*)bt)[tid];
    ((float4*)(out + (size_t)row * HD))[tid] =
        make_float4(d.x*rs*gg.x + bb.x, d.y*rs*gg.y + bb.y, d.z*rs*gg.z + bb.z, d.w*rs*gg.w + bb.w);
}

// ---------------- launch ----------------
extern "C" void kernel_launch(void* const* d_in, const int* in_sizes, int n_in,
                              void* d_out, int out_size)
{
    (void)in_sizes; (void)n_in; (void)out_size;
    const float* word = (const float*)d_in[0];
    const float* ent  = (const float*)d_in[1];
    const float* mask = (const float*)d_in[2];
    const float* qpos = (const float*)d_in[3];
    const float* Wq  = (const float*)d_in[4];   const float* bq  = (const float*)d_in[5];
    const float* Wk  = (const float*)d_in[6];   const float* bk  = (const float*)d_in[7];
    const float* Wv  = (const float*)d_in[8];   const float* bv  = (const float*)d_in[9];
    const float* Weq = (const float*)d_in[10];  const float* beq = (const float*)d_in[11];
    const float* Wek = (const float*)d_in[12];  const float* bek = (const float*)d_in[13];
    const float* Wev = (const float*)d_in[14];  const float* bev = (const float*)d_in[15];
    const float* Wo  = (const float*)d_in[16];  const float* bo  = (const float*)d_in[17];
    const float* Weo = (const float*)d_in[18];  const float* beo = (const float*)d_in[19];
    const float* lng  = (const float*)d_in[20]; const float* lnb  = (const float*)d_in[21];
    const float* elng = (const float*)d_in[22]; const float* elnb = (const float*)d_in[23];
    float* out = (float*)d_out;

    float *Y;
    __half *QH, *KH, *VH, *Xh, *Wt;
    int8_t *Xq, *W8;
    cudaGetSymbolAddress((void**)&Y,  g_Y);
    cudaGetSymbolAddress((void**)&QH, g_QH);
    cudaGetSymbolAddress((void**)&KH, g_KH);
    cudaGetSymbolAddress((void**)&VH, g_VH);
    cudaGetSymbolAddress((void**)&Xh, g_Xh);
    cudaGetSymbolAddress((void**)&Wt, g_Wt);
    cudaGetSymbolAddress((void**)&Xq, g_Xq);
    cudaGetSymbolAddress((void**)&W8, g_W8);

    cudaFuncSetAttribute(gemm_i8,  cudaFuncAttributeMaxDynamicSharedMemorySize, SMEM_GEMM);
    cudaFuncSetAttribute(gemm_mma, cudaFuncAttributeMaxDynamicSharedMemorySize, SMEM_GEMM);
    cudaFuncSetAttribute(attn_tc,  cudaFuncAttributeMaxDynamicSharedMemorySize, ATTN_SMEM);

    // 1. unified prep (int8 QKV weights + fp16 out-proj weights + int8 activations)
    PrepArgs pa;
    pa.w[0]=Wq; pa.w[1]=Wk; pa.w[2]=Wv; pa.w[3]=Weq; pa.w[4]=Wek; pa.w[5]=Wev; pa.w[6]=Wo; pa.w[7]=Weo;
    pa.word = word; pa.ent = ent; pa.qp = qpos;
    prep_kernel<<<dim3(1280, 1, 9), 256>>>(pa, W8, Wt, Xq);

    // 2. QKV projections (int8 IMMA) -> fp16 head layout
    GemmCfg cq = {};
    cq.bias0[0]=bq;  cq.bias0[1]=bk;  cq.bias0[2]=bv;
    cq.bias1[0]=beq; cq.bias1[1]=bek; cq.bias1[2]=bev;
    cq.o[0]=QH; cq.o[1]=KH; cq.o[2]=VH;
    cq.widx0 = 0; cq.widx1 = 3; cq.ySplit = (NB*TW)/128;
    cq.Tseg0 = TW; cq.toffOut0 = 0;  cq.xb01_0 = 0;    cq.xb2_0 = 0;
    cq.Tseg1 = TE; cq.toffOut1 = TW; cq.xb01_1 = 4096; cq.xb2_1 = 4608;
    gemm_i8<<<dim3(8, (NB*TW + NB*TE)/128, 3), 256, SMEM_GEMM>>>(Xq, W8, cq);

    // 3. attention (fp16) -> CTX fp16 into Xh rows [0, 4608)
    attn_tc<<<dim3(TT/128, NB*NHD), 256, ATTN_SMEM>>>(QH, KH, VH, mask, Xh);

    // 4. output projections (fp16 HMMA) + residual -> unified Y
    GemmCfg co = {};
    co.bias0[0]=bo; co.bias1[0]=beo;
    co.o[0]=Y;
    co.res0 = word; co.res1 = ent;
    co.widx0 = 0; co.widx1 = 1; co.mode = 1; co.ySplit = (NB*TW)/128;
    co.Tseg0 = TW; co.Tfull0 = TT; co.toff0 = 0;
    co.Tseg1 = TE; co.Tfull1 = TT; co.toff1 = TW;
    co.outRowBase1 = NB*TW;
    gemm_mma<<<dim3(8, (NB*TW + NB*TE)/128, 1), 256, SMEM_GEMM>>>(Xh, Wt, co);

    // 5. layernorm -> d_out
    ln_kernel<<<NB*TW + NB*TE, 256>>>(Y, lng, lnb, elng, elnb, out);
}

// round 15
// speedup vs baseline: 1.4827x; 1.4827x over previous
#include <cuda_runtime.h>
#include <cuda_bf16.h>
#include <cuda_fp16.h>
#include <stdint.h>
#include <math.h>

#define NB  4
#define TW  1024
#define TE  128
#define TT  1152
#define HD  1024
#define NHD 16
#define DHD 64

// ---------------- scratch ----------------
__device__ float  g_Y [(NB*TW + NB*TE)*HD];   // unified pre-LN temp
__device__ __half g_QH[NB*NHD*TT*DHD];        // fp16 head-layout Q (pre-scaled 0.125*log2e)
__device__ __half g_KH[NB*NHD*TT*DHD];
__device__ __half g_VH[NB*NHD*TT*DHD];
__device__ __half g_Xh[5120*1024];
__device__ __half g_Wt[8*1024*1024];

// ---------------- helpers ----------------
__device__ __forceinline__ uint32_t smem_u32(const void* p){
    uint32_t a;
    asm("{ .reg .u64 t; cvta.to.shared.u64 t, %1; cvt.u32.u64 %0, t; }" : "=r"(a) : "l"(p));
    return a;
}
__device__ __forceinline__ uint32_t pkh(float a, float b){
    __half2 h = __floats2half2_rn(a, b);
    return *reinterpret_cast<uint32_t*>(&h);
}
__device__ __forceinline__ uint32_t ex2h2(uint32_t x){
    uint32_t r; asm("ex2.approx.f16x2 %0, %1;" : "=r"(r) : "r"(x)); return r;
}
__device__ __forceinline__ uint32_t hadd2u(uint32_t a, uint32_t b){
    uint32_t r; asm("add.f16x2 %0, %1, %2;" : "=r"(r) : "r"(a), "r"(b)); return r;
}
__device__ __forceinline__ float h2sumf(uint32_t h){
    __half2 v = *reinterpret_cast<__half2*>(&h);
    float2 f = __half22float2(v);
    return f.x + f.y;
}
__device__ __forceinline__ float2 h2f2(uint32_t h){
    __half2 v = *reinterpret_cast<__half2*>(&h);
    return __half22float2(v);
}

#define CPA16(dst, src) asm volatile("cp.async.cg.shared.global [%0], [%1], 16;" :: "r"(dst), "l"(src))
#define CPA_COMMIT()    asm volatile("cp.async.commit_group;" ::: "memory")
template<int N> __device__ __forceinline__ void cpa_wait(){
    asm volatile("cp.async.wait_group %0;" :: "n"(N) : "memory");
}

__device__ __forceinline__ void ldsm4(uint32_t* r, uint32_t addr){
    asm volatile("ldmatrix.sync.aligned.m8n8.x4.shared.b16 {%0,%1,%2,%3}, [%4];"
        : "=r"(r[0]), "=r"(r[1]), "=r"(r[2]), "=r"(r[3]) : "r"(addr));
}
__device__ __forceinline__ void ldsm4t(uint32_t* r, uint32_t addr){
    asm volatile("ldmatrix.sync.aligned.m8n8.x4.trans.shared.b16 {%0,%1,%2,%3}, [%4];"
        : "=r"(r[0]), "=r"(r[1]), "=r"(r[2]), "=r"(r[3]) : "r"(addr));
}
__device__ __forceinline__ void mma16816h(float* d, const uint32_t* a, const uint32_t* b){
    asm volatile("mma.sync.aligned.m16n8k16.row.col.f32.f16.f16.f32 "
        "{%0,%1,%2,%3}, {%4,%5,%6,%7}, {%8,%9}, {%0,%1,%2,%3};"
        : "+f"(d[0]), "+f"(d[1]), "+f"(d[2]), "+f"(d[3])
        : "r"(a[0]), "r"(a[1]), "r"(a[2]), "r"(a[3]), "r"(b[0]), "r"(b[1]));
}
__device__ __forceinline__ void mma16816hh(uint32_t* d, const uint32_t* a, const uint32_t* b){
    asm volatile("mma.sync.aligned.m16n8k16.row.col.f16.f16.f16.f16 "
        "{%0,%1}, {%2,%3,%4,%5}, {%6,%7}, {%0,%1};"
        : "+r"(d[0]), "+r"(d[1])
        : "r"(a[0]), "r"(a[1]), "r"(a[2]), "r"(a[3]), "r"(b[0]), "r"(b[1]));
}

// ---------------- unified prep: weights (z<8) + activations (z==8) ----------------
struct PrepArgs {
    const float* w[8];
    const float* word; const float* ent; const float* qp;
};

__global__ __launch_bounds__(256) void prep_kernel(PrepArgs pa, __half* Wt, __half* Xh){
    __shared__ float tile[32][33];
    const int z = blockIdx.z;
    if (z < 8) {
        if (blockIdx.x >= 1024) return;
        const float* W = pa.w[z];
        int n0 = (blockIdx.x & 31) * 32, k0 = (blockIdx.x >> 5) * 32;
        int tx = threadIdx.x & 31, ty = threadIdx.x >> 5;
        #pragma unroll
        for (int i = 0; i < 32; i += 8)
            tile[ty + i][tx] = W[(size_t)(k0 + ty + i) * 1024 + n0 + tx];
        __syncthreads();
        #pragma unroll
        for (int i = 0; i < 32; i += 8) {
            float f = tile[tx][ty + i];
            size_t o = ((size_t)z << 20) + ((size_t)(n0 + ty + i) << 10) + k0 + tx;
            Wt[o] = __float2half_rn(f);
        }
    } else {
        size_t base4 = (size_t)blockIdx.x * 1024;
        #pragma unroll
        for (int i = 0; i < 4; i++) {
            size_t idx4 = base4 + threadIdx.x + i * 256;
            size_t row = idx4 >> 8;
            float4 v;
            if (row < 4096) {
                v = ((const float4*)pa.word)[idx4];
            } else if (row < 4608) {
                size_t off = idx4 - (size_t)4096 * 256;
                float4 a = ((const float4*)pa.ent)[off];
                float4 b = ((const float4*)pa.qp)[off];
                v = make_float4((a.x+b.x)*0.5f,(a.y+b.y)*0.5f,(a.z+b.z)*0.5f,(a.w+b.w)*0.5f);
            } else {
                size_t off = idx4 - (size_t)4608 * 256;
                v = ((const float4*)pa.ent)[off];
            }
            ((uint2*)Xh)[idx4] = make_uint2(pkh(v.x, v.y), pkh(v.z, v.w));
        }
    }
}

// ---------------- common geometry ----------------
#define STRB  144
#define L2E 1.44269504f

struct GemmCfg {
    const float* bias0[3]; const float* bias1[3];
    void* o[3];
    const float* res0; const float* res1;
    int widx0, widx1;
    int mode;
    int ySplit;
    int Tseg0, Tfull0, toff0, toffOut0, xb01_0, xb2_0;
    int Tseg1, Tfull1, toff1, toffOut1, xb01_1, xb2_1;
    int outRowBase1;
};

// ---------------- QKV GEMM: 128x256 tile, fp16 accumulators ----------------
#define QOFF_B 18432
#define QBUFSZ 55296            // A 18432 + B 36864
#define SMEM_QKV (2*QBUFSZ)     // 110592

__global__ __launch_bounds__(256, 2) void gemm_qkv(
    const __half* __restrict__ Xh, const __half* __restrict__ WtAll, GemmCfg cfg)
{
    extern __shared__ char smc[];
    const uint32_t sb = smem_u32(smc);
    const int tid = threadIdx.x;
    const int wid = tid >> 5, lane = tid & 31;
    const int wm = wid >> 1, wn = wid & 1;     // warp tile: M 32 x N 128
    const int z = blockIdx.z;

    const int seg = (blockIdx.y >= cfg.ySplit) ? 1 : 0;
    const int yy  = seg ? blockIdx.y - cfg.ySplit : blockIdx.y;

    const float* bias = (seg ? cfg.bias1 : cfg.bias0)[z];
    __half* out = (__half*)cfg.o[z];
    const int Tseg    = seg ? cfg.Tseg1    : cfg.Tseg0;
    const int toffOut = seg ? cfg.toffOut1 : cfg.toffOut0;
    const int xb      = (z == 2) ? (seg ? cfg.xb2_1 : cfg.xb2_0)
                                 : (seg ? cfg.xb01_1 : cfg.xb01_0);
    const int widx    = (seg ? cfg.widx1 : cfg.widx0) + z;

    const __half* Wt = WtAll + ((size_t)widx << 20);
    const float oscale = (z == 0) ? (0.125f * L2E) : 1.f;

    const int m0 = yy * 128;
    const int n0 = blockIdx.x * 256;
    const int b2 = m0 / Tseg;
    const int t0 = m0 - b2 * Tseg;
    const __half* Ah = Xh + ((size_t)(xb + m0)) * HD;

    uint32_t acc[2][16][2];
    #pragma unroll
    for (int mt = 0; mt < 2; mt++)
        #pragma unroll
        for (int nt = 0; nt < 16; nt++) { acc[mt][nt][0] = 0u; acc[mt][nt][1] = 0u; }

    auto issue_chunk = [&](int ch, int buf){
        const int k0 = ch * 64;
        const uint32_t base = sb + buf * QBUFSZ;
        #pragma unroll
        for (int i = 0; i < 4; i++) {              // A: 128 rows
            int q = tid + i * 256;
            int r = q >> 3, s8 = q & 7;
            CPA16(base + r * STRB + s8 * 16, Ah + (size_t)r * HD + k0 + s8 * 8);
        }
        #pragma unroll
        for (int i = 0; i < 8; i++) {              // B: 256 rows
            int q = tid + i * 256;
            int r = q >> 3, s8 = q & 7;
            CPA16(base + QOFF_B + r * STRB + s8 * 16, Wt + (size_t)(n0 + r) * HD + k0 + s8 * 8);
        }
    };

    issue_chunk(0, 0);
    CPA_COMMIT();

    const int arow = (lane & 7) + ((lane >> 3) & 1) * 8;
    const int acol8 = (lane >> 4) * 8;
    const int bnof = (lane & 7) + ((lane >> 4) << 3);
    const int bk8  = ((lane >> 3) & 1) * 8;

    int buf = 0;
    for (int ch = 0; ch < 16; ch++) {
        if (ch < 15) { issue_chunk(ch + 1, buf ^ 1); CPA_COMMIT(); cpa_wait<1>(); }
        else         { cpa_wait<0>(); }
        __syncthreads();

        const uint32_t base = sb + buf * QBUFSZ;
        #pragma unroll
        for (int ks = 0; ks < 4; ks++) {
            uint32_t aF[2][4];
            #pragma unroll
            for (int mt = 0; mt < 2; mt++)
                ldsm4(aF[mt], base + (wm*32 + mt*16 + arow) * STRB + (ks*16 + acol8) * 2);
            #pragma unroll
            for (int np = 0; np < 8; np++) {
                uint32_t bF[4];
                ldsm4(bF, base + QOFF_B + (wn*128 + np*16 + bnof) * STRB + (ks*16 + bk8) * 2);
                #pragma unroll
                for (int mt = 0; mt < 2; mt++) {
                    mma16816hh(acc[mt][2*np],     aF[mt], &bF[0]);
                    mma16816hh(acc[mt][2*np + 1], aF[mt], &bF[2]);
                }
            }
        }
        __syncthreads();
        buf ^= 1;
    }

    #pragma unroll
    for (int mt = 0; mt < 2; mt++) {
        #pragma unroll
        for (int hf = 0; hf < 2; hf++) {
            int lr = wm*32 + mt*16 + (lane >> 2) + hf*8;
            int t2 = t0 + lr;
            #pragma unroll
            for (int nt = 0; nt < 16; nt++) {
                int c = n0 + wn*128 + nt*8 + (lane & 3)*2;
                float2 av = h2f2(acc[mt][nt][hf]);
                float v0 = (av.x + __ldg(bias + c))     * oscale;
                float v1 = (av.y + __ldg(bias + c + 1)) * oscale;
                int h = c >> 6, d = c & 63;
                size_t o = (((size_t)(b2*NHD + h) * TT + toffOut + t2) << 6) + d;
                *(uint32_t*)(out + o) = pkh(v0, v1);
            }
        }
    }
}

// ---------------- out-proj GEMM: 128x128, fp32 acc (round-13) ----------------
#define OFF_B 18432
#define BUFSZ 36864
#define SMEM_GEMM (2*BUFSZ)

__global__ __launch_bounds__(256, 2) void gemm_mma(
    const __half* __restrict__ Xh, const __half* __restrict__ WtAll, GemmCfg cfg)
{
    extern __shared__ char smc[];
    const uint32_t sb = smem_u32(smc);
    const int tid = threadIdx.x;
    const int wid = tid >> 5, lane = tid & 31;
    const int wm = wid >> 1, wn = wid & 1;

    const int seg = (blockIdx.y >= cfg.ySplit) ? 1 : 0;
    const int yy  = seg ? blockIdx.y - cfg.ySplit : blockIdx.y;

    const float* bias = (seg ? cfg.bias1 : cfg.bias0)[0];
    float* out = (float*)cfg.o[0];
    const int Tseg  = seg ? cfg.Tseg1  : cfg.Tseg0;
    const int Tfull = seg ? cfg.Tfull1 : cfg.Tfull0;
    const int toff  = seg ? cfg.toff1  : cfg.toff0;
    const float* res  = seg ? cfg.res1 : cfg.res0;
    const int widx    = seg ? cfg.widx1 : cfg.widx0;
    const int outBase = seg ? cfg.outRowBase1 : 0;

    const __half* Wt = WtAll + ((size_t)widx << 20);

    const int m0 = yy * 128;
    const int n0 = blockIdx.x * 128;
    const int b2 = m0 / Tseg;
    const int t0 = m0 - b2 * Tseg;
    const __half* Ah = Xh + ((size_t)(b2 * Tfull + toff + t0)) * HD;

    float acc[2][8][4];
    #pragma unroll
    for (int mt = 0; mt < 2; mt++)
        #pragma unroll
        for (int nt = 0; nt < 8; nt++)
            #pragma unroll
            for (int j = 0; j < 4; j++) acc[mt][nt][j] = 0.f;

    auto issue_chunk = [&](int ch, int buf){
        const int k0 = ch * 64;
        const uint32_t base = sb + buf * BUFSZ;
        #pragma unroll
        for (int i = 0; i < 4; i++) {
            int q = tid + i * 256;
            int r = q >> 3, s8 = q & 7;
            CPA16(base + r * STRB + s8 * 16,         Ah + (size_t)r * HD + k0 + s8 * 8);
            CPA16(base + OFF_B + r * STRB + s8 * 16, Wt + (size_t)(n0 + r) * HD + k0 + s8 * 8);
        }
    };

    issue_chunk(0, 0);
    CPA_COMMIT();

    const int arow = (lane & 7) + ((lane >> 3) & 1) * 8;
    const int acol8 = (lane >> 4) * 8;
    const int bnof = (lane & 7) + ((lane >> 4) << 3);
    const int bk8  = ((lane >> 3) & 1) * 8;

    int buf = 0;
    for (int ch = 0; ch < 16; ch++) {
        if (ch < 15) { issue_chunk(ch + 1, buf ^ 1); CPA_COMMIT(); cpa_wait<1>(); }
        else         { cpa_wait<0>(); }
        __syncthreads();

        const uint32_t base = sb + buf * BUFSZ;
        #pragma unroll
        for (int ks = 0; ks < 4; ks++) {
            uint32_t aF[2][4];
            #pragma unroll
            for (int mt = 0; mt < 2; mt++)
                ldsm4(aF[mt], base + (wm*32 + mt*16 + arow) * STRB + (ks*16 + acol8) * 2);
            uint32_t bF[4][4];
            #pragma unroll
            for (int np = 0; np < 4; np++)
                ldsm4(bF[np], base + OFF_B + (wn*64 + np*16 + bnof) * STRB + (ks*16 + bk8) * 2);
            #pragma unroll
            for (int mt = 0; mt < 2; mt++)
                #pragma unroll
                for (int nt = 0; nt < 8; nt++)
                    mma16816h(acc[mt][nt], aF[mt], &bF[nt >> 1][(nt & 1) * 2]);
        }
        __syncthreads();
        buf ^= 1;
    }

    #pragma unroll
    for (int mt = 0; mt < 2; mt++) {
        #pragma unroll
        for (int hf = 0; hf < 2; hf++) {
            int lr = wm*32 + mt*16 + (lane >> 2) + hf*8;
            #pragma unroll
            for (int nt = 0; nt < 8; nt++) {
                int c = n0 + wn*64 + nt*8 + (lane & 3)*2;
                float v0 = acc[mt][nt][hf*2+0] + __ldg(bias + c);
                float v1 = acc[mt][nt][hf*2+1] + __ldg(bias + c + 1);
                size_t ro = (size_t)(m0 + lr) * HD + c;
                float2 rr = *(const float2*)(res + ro);
                size_t oo = (size_t)(outBase + m0 + lr) * HD + c;
                *(float2*)(out + oo) = make_float2(v0 + rr.x, v1 + rr.y);
            }
        }
    }
}

// ---------------- fp16 flash attention (round-13 best) ----------------
#define AO_KF 18432
#define AO_VF 55296
#define AO_MK 92160
#define ATTN_SMEM 96768

__global__ __launch_bounds__(256, 2) void attn_tc(
    const __half* __restrict__ Q, const __half* __restrict__ K,
    const __half* __restrict__ V, const float* __restrict__ mask,
    __half* __restrict__ OutH)
{
    extern __shared__ char smc[];
    const uint32_t sbase = smem_u32(smc);
    float* mks = (float*)(smc + AO_MK);

    const int tid = threadIdx.x, wid = tid >> 5, lane = tid & 31;
    const int bh = blockIdx.y, b = bh >> 4, h = bh & 15;
    const int q0 = blockIdx.x * 128;
    const __half* Qg = Q + ((size_t)bh * TT + q0) * DHD;
    const __half* Kg = K + (size_t)bh * TT * DHD;
    const __half* Vg = V + (size_t)bh * TT * DHD;
    const float* mb = mask + (size_t)b * TT;

    auto loadQ = [&](){
        #pragma unroll
        for (int i = 0; i < 4; i++) {
            int q = tid + i * 256;
            int r = q >> 3, s = q & 7;
            CPA16(sbase + r * STRB + s * 16, Qg + (size_t)r * DHD + s * 8);
        }
    };
    auto issueKV = [&](int ch, int buf){
        const __half* ks = Kg + (size_t)ch * 128 * DHD;
        const __half* vs = Vg + (size_t)ch * 128 * DHD;
        uint32_t kd = sbase + AO_KF + buf * 18432;
        uint32_t vd = sbase + AO_VF + buf * 18432;
        #pragma unroll
        for (int i = 0; i < 4; i++) {
            int q = tid + i * 256;
            int r = q >> 3, s = q & 7;
            CPA16(kd + r * STRB + s * 16, ks + (size_t)r * DHD + s * 8);
            CPA16(vd + r * STRB + s * 16, vs + (size_t)r * DHD + s * 8);
        }
        CPA_COMMIT();
    };

    loadQ();
    issueKV(0, 0);

    #pragma unroll
    for (int i = 0; i < 5; i++) {
        int idx = tid + i * 256;
        if (idx < TT) mks[idx] = __ldg(mb + idx) * L2E;
    }

    const int r4 = lane >> 2, c4 = lane & 3;
    const int row0 = wid * 16 + r4;
    const int arow16 = lane & 15, acol8 = (lane >> 4) * 8;
    const int bnof = (lane & 7) + ((lane >> 4) << 3);
    const int bk8  = ((lane >> 3) & 1) * 8;
    const int vgrp = lane >> 3, vwi = lane & 7;

    float O[8][4];
    #pragma unroll
    for (int nt = 0; nt < 8; nt++)
        #pragma unroll
        for (int j = 0; j < 4; j++) O[nt][j] = 0.f;
    float m0 = -1e30f, m1 = -1e30f, l0 = 0.f, l1 = 0.f;

    int buf = 0;
    for (int ch = 0; ch < 9; ch++) {
        if (ch > 0) __syncthreads();
        if (ch < 8) { issueKV(ch + 1, buf ^ 1); cpa_wait<1>(); }
        else        { cpa_wait<0>(); }
        __syncthreads();

        const uint32_t kb = sbase + AO_KF + buf * 18432;
        const uint32_t vb = sbase + AO_VF + buf * 18432;

        float S[16][4];
        #pragma unroll
        for (int nt = 0; nt < 16; nt++)
            #pragma unroll
            for (int j = 0; j < 4; j++) S[nt][j] = 0.f;

        {
            uint32_t aQ[4][4];
            #pragma unroll
            for (int ks = 0; ks < 4; ks++)
                ldsm4(aQ[ks], sbase + (wid*16 + arow16) * STRB + (ks*16 + acol8) * 2);
            #pragma unroll
            for (int ntp = 0; ntp < 8; ntp++) {
                #pragma unroll
                for (int ks = 0; ks < 4; ks++) {
                    uint32_t bF[4];
                    ldsm4(bF, kb + (ntp*16 + bnof) * STRB + (ks*16 + bk8) * 2);
                    mma16816h(S[2*ntp],     aQ[ks], &bF[0]);
                    mma16816h(S[2*ntp + 1], aQ[ks], &bF[2]);
                }
            }
        }

        const int kgl = ch * 128;
        float mt0 = -1e30f, mt1 = -1e30f;
        #pragma unroll
        for (int nt = 0; nt < 16; nt++) {
            float mkx = mks[kgl + nt*8 + 2*c4];
            float mky = mks[kgl + nt*8 + 2*c4 + 1];
            S[nt][0] += mkx;
            S[nt][1] += mky;
            S[nt][2] += mkx;
            S[nt][3] += mky;
            mt0 = fmaxf(mt0, fmaxf(S[nt][0], S[nt][1]));
            mt1 = fmaxf(mt1, fmaxf(S[nt][2], S[nt][3]));
        }
        mt0 = fmaxf(mt0, __shfl_xor_sync(0xffffffffu, mt0, 1));
        mt0 = fmaxf(mt0, __shfl_xor_sync(0xffffffffu, mt0, 2));
        mt1 = fmaxf(mt1, __shfl_xor_sync(0xffffffffu, mt1, 1));
        mt1 = fmaxf(mt1, __shfl_xor_sync(0xffffffffu, mt1, 2));

        float mn0 = fmaxf(m0, mt0), mn1 = fmaxf(m1, mt1);
        float al0 = exp2f(m0 - mn0), al1 = exp2f(m1 - mn1);
        #pragma unroll
        for (int nt = 0; nt < 8; nt++) {
            O[nt][0] *= al0; O[nt][1] *= al0;
            O[nt][2] *= al1; O[nt][3] *= al1;
        }

        uint32_t la0 = 0u, lb0 = 0u, la1 = 0u, lb1 = 0u;
        #pragma unroll
        for (int t = 0; t < 8; t++) {
            uint32_t P[4];
            P[0] = ex2h2(pkh(S[2*t][0]   - mn0, S[2*t][1]   - mn0));
            P[1] = ex2h2(pkh(S[2*t][2]   - mn1, S[2*t][3]   - mn1));
            P[2] = ex2h2(pkh(S[2*t+1][0] - mn0, S[2*t+1][1] - mn0));
            P[3] = ex2h2(pkh(S[2*t+1][2] - mn1, S[2*t+1][3] - mn1));
            uint32_t p02 = hadd2u(P[0], P[2]);
            uint32_t p13 = hadd2u(P[1], P[3]);
            if (t & 1) { lb0 = hadd2u(lb0, p02); lb1 = hadd2u(lb1, p13); }
            else       { la0 = hadd2u(la0, p02); la1 = hadd2u(la1, p13); }
            #pragma unroll
            for (int dp = 0; dp < 4; dp++) {
                uint32_t bF[4];
                ldsm4t(bF, vb + (t*16 + (vgrp & 1)*8 + vwi) * STRB + (dp*16 + (vgrp >> 1)*8) * 2);
                mma16816h(O[2*dp],     P, &bF[0]);
                mma16816h(O[2*dp + 1], P, &bF[2]);
            }
        }
        {
            float ls0 = h2sumf(hadd2u(la0, lb0));
            float ls1 = h2sumf(hadd2u(la1, lb1));
            ls0 += __shfl_xor_sync(0xffffffffu, ls0, 1);
            ls0 += __shfl_xor_sync(0xffffffffu, ls0, 2);
            ls1 += __shfl_xor_sync(0xffffffffu, ls1, 1);
            ls1 += __shfl_xor_sync(0xffffffffu, ls1, 2);
            l0 = l0 * al0 + ls0; m0 = mn0;
            l1 = l1 * al1 + ls1; m1 = mn1;
        }
        buf ^= 1;
    }

    float i0 = 1.f / l0, i1 = 1.f / l1;
    #pragma unroll
    for (int nt = 0; nt < 8; nt++) {
        int c = h * 64 + nt*8 + 2*c4;
        size_t o0 = (size_t)(b * TT + q0 + row0) * HD + c;
        size_t o1 = (size_t)(b * TT + q0 + row0 + 8) * HD + c;
        *(uint32_t*)(OutH + o0) = pkh(O[nt][0] * i0, O[nt][1] * i0);
        *(uint32_t*)(OutH + o1) = pkh(O[nt][2] * i1, O[nt][3] * i1);
    }
}

// ---------------- layernorm ----------------
__device__ __forceinline__ float block_sum(float v, float* sh) {
    #pragma unroll
    for (int o = 16; o; o >>= 1) v += __shfl_xor_sync(0xffffffffu, v, o);
    int tid = threadIdx.x;
    if ((tid & 31) == 0) sh[tid >> 5] = v;
    __syncthreads();
    if (tid < 32) {
        float t = (tid < 8) ? sh[tid] : 0.f;
        #pragma unroll
        for (int o = 4; o; o >>= 1) t += __shfl_xor_sync(0xffffffffu, t, o);
        if (tid == 0) sh[0] = t;
    }
    __syncthreads();
    float r = sh[0];
    __syncthreads();
    return r;
}

__global__ __launch_bounds__(256) void ln_kernel(
    const float* __restrict__ Y,
    const float* __restrict__ g0, const float* __restrict__ b0,
    const float* __restrict__ g1, const float* __restrict__ b1,
    float* __restrict__ out)
{
    __shared__ float sh[8];
    int row = blockIdx.x, tid = threadIdx.x;
    const float* g  = (row < NB*TW) ? g0 : g1;
    const float* bt = (row < NB*TW) ? b0 : b1;
    float4 v = ((const float4*)(Y + (size_t)row * HD))[tid];
    float mu = block_sum(v.x + v.y + v.z + v.w, sh) * (1.f / HD);
    float4 d = make_float4(v.x - mu, v.y - mu, v.z - mu, v.w - mu);
    float var = block_sum(d.x*d.x + d.y*d.y + d.z*d.z + d.w*d.w, sh) * (1.f / HD);
    float rs = rsqrtf(var + 1e-12f);
    float4 gg = ((const float4*)g)[tid];
    float4 bb = ((const float4*)bt)[tid];
    ((float4*)(out + (size_t)row * HD))[tid] =
        make_float4(d.x*rs*gg.x + bb.x, d.y*rs*gg.y + bb.y, d.z*rs*gg.z + bb.z, d.w*rs*gg.w + bb.w);
}

// ---------------- launch ----------------
extern "C" void kernel_launch(void* const* d_in, const int* in_sizes, int n_in,
                              void* d_out, int out_size)
{
    (void)in_sizes; (void)n_in; (void)out_size;
    const float* word = (const float*)d_in[0];
    const float* ent  = (const float*)d_in[1];
    const float* mask = (const float*)d_in[2];
    const float* qpos = (const float*)d_in[3];
    const float* Wq  = (const float*)d_in[4];   const float* bq  = (const float*)d_in[5];
    const float* Wk  = (const float*)d_in[6];   const float* bk  = (const float*)d_in[7];
    const float* Wv  = (const float*)d_in[8];   const float* bv  = (const float*)d_in[9];
    const float* Weq = (const float*)d_in[10];  const float* beq = (const float*)d_in[11];
    const float* Wek = (const float*)d_in[12];  const float* bek = (const float*)d_in[13];
    const float* Wev = (const float*)d_in[14];  const float* bev = (const float*)d_in[15];
    const float* Wo  = (const float*)d_in[16];  const float* bo  = (const float*)d_in[17];
    const float* Weo = (const float*)d_in[18];  const float* beo = (const float*)d_in[19];
    const float* lng  = (const float*)d_in[20]; const float* lnb  = (const float*)d_in[21];
    const float* elng = (const float*)d_in[22]; const float* elnb = (const float*)d_in[23];
    float* out = (float*)d_out;

    float *Y;
    __half *QH, *KH, *VH, *Xh, *Wt;
    cudaGetSymbolAddress((void**)&Y,  g_Y);
    cudaGetSymbolAddress((void**)&QH, g_QH);
    cudaGetSymbolAddress((void**)&KH, g_KH);
    cudaGetSymbolAddress((void**)&VH, g_VH);
    cudaGetSymbolAddress((void**)&Xh, g_Xh);
    cudaGetSymbolAddress((void**)&Wt, g_Wt);

    cudaFuncSetAttribute(gemm_qkv, cudaFuncAttributeMaxDynamicSharedMemorySize, SMEM_QKV);
    cudaFuncSetAttribute(gemm_mma, cudaFuncAttributeMaxDynamicSharedMemorySize, SMEM_GEMM);
    cudaFuncSetAttribute(attn_tc,  cudaFuncAttributeMaxDynamicSharedMemorySize, ATTN_SMEM);

    // 1. unified prep
    PrepArgs pa;
    pa.w[0]=Wq; pa.w[1]=Wk; pa.w[2]=Wv; pa.w[3]=Weq; pa.w[4]=Wek; pa.w[5]=Wev; pa.w[6]=Wo; pa.w[7]=Weo;
    pa.word = word; pa.ent = ent; pa.qp = qpos;
    prep_kernel<<<dim3(1280, 1, 9), 256>>>(pa, Wt, Xh);

    // 2. QKV projections (128x256 fp16-acc) -> fp16 head layout
    GemmCfg cq = {};
    cq.bias0[0]=bq;  cq.bias0[1]=bk;  cq.bias0[2]=bv;
    cq.bias1[0]=beq; cq.bias1[1]=bek; cq.bias1[2]=bev;
    cq.o[0]=QH; cq.o[1]=KH; cq.o[2]=VH;
    cq.widx0 = 0; cq.widx1 = 3; cq.ySplit = (NB*TW)/128;
    cq.Tseg0 = TW; cq.toffOut0 = 0;  cq.xb01_0 = 0;    cq.xb2_0 = 0;
    cq.Tseg1 = TE; cq.toffOut1 = TW; cq.xb01_1 = 4096; cq.xb2_1 = 4608;
    gemm_qkv<<<dim3(4, (NB*TW + NB*TE)/128, 3), 256, SMEM_QKV>>>(Xh, Wt, cq);

    // 3. attention (fp16, base-2 softmax) -> CTX fp16 into Xh rows [0, 4608)
    attn_tc<<<dim3(TT/128, NB*NHD), 256, ATTN_SMEM>>>(QH, KH, VH, mask, Xh);

    // 4. output projections + residual -> unified Y
    GemmCfg co = {};
    co.bias0[0]=bo; co.bias1[0]=beo;
    co.o[0]=Y;
    co.res0 = word; co.res1 = ent;
    co.widx0 = 6; co.widx1 = 7; co.mode = 1; co.ySplit = (NB*TW)/128;
    co.Tseg0 = TW; co.Tfull0 = TT; co.toff0 = 0;
    co.Tseg1 = TE; co.Tfull1 = TT; co.toff1 = TW;
    co.outRowBase1 = NB*TW;
    gemm_mma<<<dim3(8, (NB*TW + NB*TE)/128, 1), 256, SMEM_GEMM>>>(Xh, Wt, co);

    // 5. layernorm -> d_out
    ln_kernel<<<NB*TW + NB*TE, 256>>>(Y, lng, lnb, elng, elnb, out);
}

// round 17
// speedup vs baseline: 1.5105x; 1.0188x over previous
#include <cuda_runtime.h>
#include <cuda_bf16.h>
#include <cuda_fp16.h>
#include <stdint.h>
#include <math.h>

#define NB  4
#define TW  1024
#define TE  128
#define TT  1152
#define HD  1024
#define NHD 16
#define DHD 64

// ---------------- scratch ----------------
__device__ float  g_Y [(NB*TW + NB*TE)*HD];
__device__ __half g_QH[NB*NHD*TT*DHD];
__device__ __half g_KH[NB*NHD*TT*DHD];
__device__ __half g_VH[NB*NHD*TT*DHD];
__device__ __half g_Xh[5120*1024];
__device__ __half g_Wt[8*1024*1024];

// ---------------- helpers ----------------
__device__ __forceinline__ uint32_t smem_u32(const void* p){
    uint32_t a;
    asm("{ .reg .u64 t; cvta.to.shared.u64 t, %1; cvt.u32.u64 %0, t; }" : "=r"(a) : "l"(p));
    return a;
}
__device__ __forceinline__ uint32_t pkh(float a, float b){
    __half2 h = __floats2half2_rn(a, b);
    return *reinterpret_cast<uint32_t*>(&h);
}
__device__ __forceinline__ uint32_t ex2h2(uint32_t x){
    uint32_t r; asm("ex2.approx.f16x2 %0, %1;" : "=r"(r) : "r"(x)); return r;
}
__device__ __forceinline__ uint32_t hadd2u(uint32_t a, uint32_t b){
    uint32_t r; asm("add.f16x2 %0, %1, %2;" : "=r"(r) : "r"(a), "r"(b)); return r;
}
__device__ __forceinline__ float h2sumf(uint32_t h){
    __half2 v = *reinterpret_cast<__half2*>(&h);
    float2 f = __half22float2(v);
    return f.x + f.y;
}
__device__ __forceinline__ float2 h2f2(uint32_t h){
    __half2 v = *reinterpret_cast<__half2*>(&h);
    return __half22float2(v);
}

#define CPA16(dst, src) asm volatile("cp.async.cg.shared.global [%0], [%1], 16;" :: "r"(dst), "l"(src))
#define CPA_COMMIT()    asm volatile("cp.async.commit_group;" ::: "memory")
template<int N> __device__ __forceinline__ void cpa_wait(){
    asm volatile("cp.async.wait_group %0;" :: "n"(N) : "memory");
}

__device__ __forceinline__ void ldsm4(uint32_t* r, uint32_t addr){
    asm volatile("ldmatrix.sync.aligned.m8n8.x4.shared.b16 {%0,%1,%2,%3}, [%4];"
        : "=r"(r[0]), "=r"(r[1]), "=r"(r[2]), "=r"(r[3]) : "r"(addr));
}
__device__ __forceinline__ void ldsm4t(uint32_t* r, uint32_t addr){
    asm volatile("ldmatrix.sync.aligned.m8n8.x4.trans.shared.b16 {%0,%1,%2,%3}, [%4];"
        : "=r"(r[0]), "=r"(r[1]), "=r"(r[2]), "=r"(r[3]) : "r"(addr));
}
__device__ __forceinline__ void mma16816h(float* d, const uint32_t* a, const uint32_t* b){
    asm volatile("mma.sync.aligned.m16n8k16.row.col.f32.f16.f16.f32 "
        "{%0,%1,%2,%3}, {%4,%5,%6,%7}, {%8,%9}, {%0,%1,%2,%3};"
        : "+f"(d[0]), "+f"(d[1]), "+f"(d[2]), "+f"(d[3])
        : "r"(a[0]), "r"(a[1]), "r"(a[2]), "r"(a[3]), "r"(b[0]), "r"(b[1]));
}
__device__ __forceinline__ void mma16816hh(uint32_t* d, const uint32_t* a, const uint32_t* b){
    asm volatile("mma.sync.aligned.m16n8k16.row.col.f16.f16.f16.f16 "
        "{%0,%1}, {%2,%3,%4,%5}, {%6,%7}, {%0,%1};"
        : "+r"(d[0]), "+r"(d[1])
        : "r"(a[0]), "r"(a[1]), "r"(a[2]), "r"(a[3]), "r"(b[0]), "r"(b[1]));
}

// ---------------- unified prep ----------------
struct PrepArgs {
    const float* w[8];
    const float* word; const float* ent; const float* qp;
};

__global__ __launch_bounds__(256) void prep_kernel(PrepArgs pa, __half* Wt, __half* Xh){
    __shared__ float tile[32][33];
    const int z = blockIdx.z;
    if (z < 8) {
        if (blockIdx.x >= 1024) return;
        const float* W = pa.w[z];
        int n0 = (blockIdx.x & 31) * 32, k0 = (blockIdx.x >> 5) * 32;
        int tx = threadIdx.x & 31, ty = threadIdx.x >> 5;
        #pragma unroll
        for (int i = 0; i < 32; i += 8)
            tile[ty + i][tx] = W[(size_t)(k0 + ty + i) * 1024 + n0 + tx];
        __syncthreads();
        #pragma unroll
        for (int i = 0; i < 32; i += 8) {
            float f = tile[tx][ty + i];
            size_t o = ((size_t)z << 20) + ((size_t)(n0 + ty + i) << 10) + k0 + tx;
            Wt[o] = __float2half_rn(f);
        }
    } else {
        size_t base4 = (size_t)blockIdx.x * 1024;
        #pragma unroll
        for (int i = 0; i < 4; i++) {
            size_t idx4 = base4 + threadIdx.x + i * 256;
            size_t row = idx4 >> 8;
            float4 v;
            if (row < 4096) {
                v = ((const float4*)pa.word)[idx4];
            } else if (row < 4608) {
                size_t off = idx4 - (size_t)4096 * 256;
                float4 a = ((const float4*)pa.ent)[off];
                float4 b = ((const float4*)pa.qp)[off];
                v = make_float4((a.x+b.x)*0.5f,(a.y+b.y)*0.5f,(a.z+b.z)*0.5f,(a.w+b.w)*0.5f);
            } else {
                size_t off = idx4 - (size_t)4608 * 256;
                v = ((const float4*)pa.ent)[off];
            }
            ((uint2*)Xh)[idx4] = make_uint2(pkh(v.x, v.y), pkh(v.z, v.w));
        }
    }
}

// ---------------- common geometry ----------------
#define STRB  144
#define L2E 1.44269504f

struct GemmCfg {
    const float* bias0[3]; const float* bias1[3];
    void* o[3];
    const float* res0; const float* res1;
    int widx0, widx1;
    int mode;
    int ySplit;
    int Tseg0, Tfull0, toff0, toffOut0, xb01_0, xb2_0;
    int Tseg1, Tfull1, toff1, toffOut1, xb01_1, xb2_1;
    int outRowBase1;
};

// ---------------- QKV GEMM: 128x256 tile, fp16 acc, staged coalesced epilogue ----------------
#define QOFF_B 18432
#define QBUFSZ 55296
#define SMEM_QKV (2*QBUFSZ)     // 110592
#define SGS 280                 // stage stride in halves (560B, 16B-aligned)

__global__ __launch_bounds__(256, 2) void gemm_qkv(
    const __half* __restrict__ Xh, const __half* __restrict__ WtAll, GemmCfg cfg)
{
    extern __shared__ char smc[];
    const uint32_t sb = smem_u32(smc);
    const int tid = threadIdx.x;
    const int wid = tid >> 5, lane = tid & 31;
    const int wm = wid >> 1, wn = wid & 1;
    const int z = blockIdx.z;

    const int seg = (blockIdx.y >= cfg.ySplit) ? 1 : 0;
    const int yy  = seg ? blockIdx.y - cfg.ySplit : blockIdx.y;

    const float* bias = (seg ? cfg.bias1 : cfg.bias0)[z];
    __half* out = (__half*)cfg.o[z];
    const int Tseg    = seg ? cfg.Tseg1    : cfg.Tseg0;
    const int toffOut = seg ? cfg.toffOut1 : cfg.toffOut0;
    const int xb      = (z == 2) ? (seg ? cfg.xb2_1 : cfg.xb2_0)
                                 : (seg ? cfg.xb01_1 : cfg.xb01_0);
    const int widx    = (seg ? cfg.widx1 : cfg.widx0) + z;

    const __half* Wt = WtAll + ((size_t)widx << 20);
    const float oscale = (z == 0) ? (0.125f * L2E) : 1.f;

    const int m0 = yy * 128;
    const int n0 = blockIdx.x * 256;
    const int b2 = m0 / Tseg;
    const int t0 = m0 - b2 * Tseg;
    const __half* Ah = Xh + ((size_t)(xb + m0)) * HD;

    uint32_t acc[2][16][2];
    #pragma unroll
    for (int mt = 0; mt < 2; mt++)
        #pragma unroll
        for (int nt = 0; nt < 16; nt++) { acc[mt][nt][0] = 0u; acc[mt][nt][1] = 0u; }

    auto issue_chunk = [&](int ch, int buf){
        const int k0 = ch * 64;
        const uint32_t base = sb + buf * QBUFSZ;
        #pragma unroll
        for (int i = 0; i < 4; i++) {
            int q = tid + i * 256;
            int r = q >> 3, s8 = q & 7;
            CPA16(base + r * STRB + s8 * 16, Ah + (size_t)r * HD + k0 + s8 * 8);
        }
        #pragma unroll
        for (int i = 0; i < 8; i++) {
            int q = tid + i * 256;
            int r = q >> 3, s8 = q & 7;
            CPA16(base + QOFF_B + r * STRB + s8 * 16, Wt + (size_t)(n0 + r) * HD + k0 + s8 * 8);
        }
    };

    issue_chunk(0, 0);
    CPA_COMMIT();

    const int arow = (lane & 7) + ((lane >> 3) & 1) * 8;
    const int acol8 = (lane >> 4) * 8;
    const int bnof = (lane & 7) + ((lane >> 4) << 3);
    const int bk8  = ((lane >> 3) & 1) * 8;

    int buf = 0;
    for (int ch = 0; ch < 16; ch++) {
        if (ch < 15) { issue_chunk(ch + 1, buf ^ 1); CPA_COMMIT(); cpa_wait<1>(); }
        else         { cpa_wait<0>(); }
        __syncthreads();

        const uint32_t base = sb + buf * QBUFSZ;
        #pragma unroll
        for (int ks = 0; ks < 4; ks++) {
            uint32_t aF[2][4];
            #pragma unroll
            for (int mt = 0; mt < 2; mt++)
                ldsm4(aF[mt], base + (wm*32 + mt*16 + arow) * STRB + (ks*16 + acol8) * 2);
            #pragma unroll
            for (int np = 0; np < 8; np++) {
                uint32_t bF[4];
                ldsm4(bF, base + QOFF_B + (wn*128 + np*16 + bnof) * STRB + (ks*16 + bk8) * 2);
                #pragma unroll
                for (int mt = 0; mt < 2; mt++) {
                    mma16816hh(acc[mt][2*np],     aF[mt], &bF[0]);
                    mma16816hh(acc[mt][2*np + 1], aF[mt], &bF[2]);
                }
            }
        }
        __syncthreads();
        buf ^= 1;
    }

    // ---- staged epilogue: SMEM tile -> coalesced global ----
    __half* stg = (__half*)smc;
    #pragma unroll
    for (int mt = 0; mt < 2; mt++) {
        #pragma unroll
        for (int hf = 0; hf < 2; hf++) {
            int lr = wm*32 + mt*16 + (lane >> 2) + hf*8;
            #pragma unroll
            for (int nt = 0; nt < 16; nt++) {
                int cc = wn*128 + nt*8 + (lane & 3)*2;
                float2 av = h2f2(acc[mt][nt][hf]);
                float v0 = (av.x + __ldg(bias + n0 + cc))     * oscale;
                float v1 = (av.y + __ldg(bias + n0 + cc + 1)) * oscale;
                *(uint32_t*)(stg + lr * SGS + cc) = pkh(v0, v1);
            }
        }
    }
    __syncthreads();
    #pragma unroll
    for (int i = 0; i < 16; i++) {
        int idx = tid + i * 256;          // 4096 chunks of 8 halves (16B)
        int r = idx >> 5, ck = idx & 31;
        uint4 val = *(const uint4*)(stg + r * SGS + ck * 8);
        int c = n0 + ck * 8;
        int h = c >> 6, d = c & 63;
        size_t o = (((size_t)(b2*NHD + h) * TT + toffOut + t0 + r) << 6) + d;
        *(uint4*)(out + o) = val;
    }
}

// ---------------- out-proj GEMM: 128x128, fp32 acc ----------------
#define OFF_B 18432
#define BUFSZ 36864
#define SMEM_GEMM (2*BUFSZ)

__global__ __launch_bounds__(256, 2) void gemm_mma(
    const __half* __restrict__ Xh, const __half* __restrict__ WtAll, GemmCfg cfg)
{
    extern __shared__ char smc[];
    const uint32_t sb = smem_u32(smc);
    const int tid = threadIdx.x;
    const int wid = tid >> 5, lane = tid & 31;
    const int wm = wid >> 1, wn = wid & 1;

    const int seg = (blockIdx.y >= cfg.ySplit) ? 1 : 0;
    const int yy  = seg ? blockIdx.y - cfg.ySplit : blockIdx.y;

    const float* bias = (seg ? cfg.bias1 : cfg.bias0)[0];
    float* out = (float*)cfg.o[0];
    const int Tseg  = seg ? cfg.Tseg1  : cfg.Tseg0;
    const int Tfull = seg ? cfg.Tfull1 : cfg.Tfull0;
    const int toff  = seg ? cfg.toff1  : cfg.toff0;
    const float* res  = seg ? cfg.res1 : cfg.res0;
    const int widx    = seg ? cfg.widx1 : cfg.widx0;
    const int outBase = seg ? cfg.outRowBase1 : 0;

    const __half* Wt = WtAll + ((size_t)widx << 20);

    const int m0 = yy * 128;
    const int n0 = blockIdx.x * 128;
    const int b2 = m0 / Tseg;
    const int t0 = m0 - b2 * Tseg;
    const __half* Ah = Xh + ((size_t)(b2 * Tfull + toff + t0)) * HD;

    float acc[2][8][4];
    #pragma unroll
    for (int mt = 0; mt < 2; mt++)
        #pragma unroll
        for (int nt = 0; nt < 8; nt++)
            #pragma unroll
            for (int j = 0; j < 4; j++) acc[mt][nt][j] = 0.f;

    auto issue_chunk = [&](int ch, int buf){
        const int k0 = ch * 64;
        const uint32_t base = sb + buf * BUFSZ;
        #pragma unroll
        for (int i = 0; i < 4; i++) {
            int q = tid + i * 256;
            int r = q >> 3, s8 = q & 7;
            CPA16(base + r * STRB + s8 * 16,         Ah + (size_t)r * HD + k0 + s8 * 8);
            CPA16(base + OFF_B + r * STRB + s8 * 16, Wt + (size_t)(n0 + r) * HD + k0 + s8 * 8);
        }
    };

    issue_chunk(0, 0);
    CPA_COMMIT();

    const int arow = (lane & 7) + ((lane >> 3) & 1) * 8;
    const int acol8 = (lane >> 4) * 8;
    const int bnof = (lane & 7) + ((lane >> 4) << 3);
    const int bk8  = ((lane >> 3) & 1) * 8;

    int buf = 0;
    for (int ch = 0; ch < 16; ch++) {
        if (ch < 15) { issue_chunk(ch + 1, buf ^ 1); CPA_COMMIT(); cpa_wait<1>(); }
        else         { cpa_wait<0>(); }
        __syncthreads();

        const uint32_t base = sb + buf * BUFSZ;
        #pragma unroll
        for (int ks = 0; ks < 4; ks++) {
            uint32_t aF[2][4];
            #pragma unroll
            for (int mt = 0; mt < 2; mt++)
                ldsm4(aF[mt], base + (wm*32 + mt*16 + arow) * STRB + (ks*16 + acol8) * 2);
            uint32_t bF[4][4];
            #pragma unroll
            for (int np = 0; np < 4; np++)
                ldsm4(bF[np], base + OFF_B + (wn*64 + np*16 + bnof) * STRB + (ks*16 + bk8) * 2);
            #pragma unroll
            for (int mt = 0; mt < 2; mt++)
                #pragma unroll
                for (int nt = 0; nt < 8; nt++)
                    mma16816h(acc[mt][nt], aF[mt], &bF[nt >> 1][(nt & 1) * 2]);
        }
        __syncthreads();
        buf ^= 1;
    }

    #pragma unroll
    for (int mt = 0; mt < 2; mt++) {
        #pragma unroll
        for (int hf = 0; hf < 2; hf++) {
            int lr = wm*32 + mt*16 + (lane >> 2) + hf*8;
            #pragma unroll
            for (int nt = 0; nt < 8; nt++) {
                int c = n0 + wn*64 + nt*8 + (lane & 3)*2;
                float v0 = acc[mt][nt][hf*2+0] + __ldg(bias + c);
                float v1 = acc[mt][nt][hf*2+1] + __ldg(bias + c + 1);
                size_t ro = (size_t)(m0 + lr) * HD + c;
                float2 rr = *(const float2*)(res + ro);
                size_t oo = (size_t)(outBase + m0 + lr) * HD + c;
                *(float2*)(out + oo) = make_float2(v0 + rr.x, v1 + rr.y);
            }
        }
    }
}

// ---------------- fp16 flash attention (staged coalesced epilogue) ----------------
#define AO_KF 18432
#define AO_VF 55296
#define AO_MK 92160
#define ATTN_SMEM 96768

__global__ __launch_bounds__(256, 2) void attn_tc(
    const __half* __restrict__ Q, const __half* __restrict__ K,
    const __half* __restrict__ V, const float* __restrict__ mask,
    __half* __restrict__ OutH)
{
    extern __shared__ char smc[];
    const uint32_t sbase = smem_u32(smc);
    float* mks = (float*)(smc + AO_MK);

    const int tid = threadIdx.x, wid = tid >> 5, lane = tid & 31;
    const int bh = blockIdx.y, b = bh >> 4, h = bh & 15;
    const int q0 = blockIdx.x * 128;
    const __half* Qg = Q + ((size_t)bh * TT + q0) * DHD;
    const __half* Kg = K + (size_t)bh * TT * DHD;
    const __half* Vg = V + (size_t)bh * TT * DHD;
    const float* mb = mask + (size_t)b * TT;

    auto loadQ = [&](){
        #pragma unroll
        for (int i = 0; i < 4; i++) {
            int q = tid + i * 256;
            int r = q >> 3, s = q & 7;
            CPA16(sbase + r * STRB + s * 16, Qg + (size_t)r * DHD + s * 8);
        }
    };
    auto issueKV = [&](int ch, int buf){
        const __half* ks = Kg + (size_t)ch * 128 * DHD;
        const __half* vs = Vg + (size_t)ch * 128 * DHD;
        uint32_t kd = sbase + AO_KF + buf * 18432;
        uint32_t vd = sbase + AO_VF + buf * 18432;
        #pragma unroll
        for (int i = 0; i < 4; i++) {
            int q = tid + i * 256;
            int r = q >> 3, s = q & 7;
            CPA16(kd + r * STRB + s * 16, ks + (size_t)r * DHD + s * 8);
            CPA16(vd + r * STRB + s * 16, vs + (size_t)r * DHD + s * 8);
        }
        CPA_COMMIT();
    };

    loadQ();
    issueKV(0, 0);

    #pragma unroll
    for (int i = 0; i < 5; i++) {
        int idx = tid + i * 256;
        if (idx < TT) mks[idx] = __ldg(mb + idx) * L2E;
    }

    const int r4 = lane >> 2, c4 = lane & 3;
    const int row0 = wid * 16 + r4;
    const int arow16 = lane & 15, acol8 = (lane >> 4) * 8;
    const int bnof = (lane & 7) + ((lane >> 4) << 3);
    const int bk8  = ((lane >> 3) & 1) * 8;
    const int vgrp = lane >> 3, vwi = lane & 7;

    float O[8][4];
    #pragma unroll
    for (int nt = 0; nt < 8; nt++)
        #pragma unroll
        for (int j = 0; j < 4; j++) O[nt][j] = 0.f;
    float m0 = -1e30f, m1 = -1e30f, l0 = 0.f, l1 = 0.f;

    int buf = 0;
    for (int ch = 0; ch < 9; ch++) {
        if (ch > 0) __syncthreads();
        if (ch < 8) { issueKV(ch + 1, buf ^ 1); cpa_wait<1>(); }
        else        { cpa_wait<0>(); }
        __syncthreads();

        const uint32_t kb = sbase + AO_KF + buf * 18432;
        const uint32_t vb = sbase + AO_VF + buf * 18432;

        float S[16][4];
        #pragma unroll
        for (int nt = 0; nt < 16; nt++)
            #pragma unroll
            for (int j = 0; j < 4; j++) S[nt][j] = 0.f;

        {
            uint32_t aQ[4][4];
            #pragma unroll
            for (int ks = 0; ks < 4; ks++)
                ldsm4(aQ[ks], sbase + (wid*16 + arow16) * STRB + (ks*16 + acol8) * 2);
            #pragma unroll
            for (int ntp = 0; ntp < 8; ntp++) {
                #pragma unroll
                for (int ks = 0; ks < 4; ks++) {
                    uint32_t bF[4];
                    ldsm4(bF, kb + (ntp*16 + bnof) * STRB + (ks*16 + bk8) * 2);
                    mma16816h(S[2*ntp],     aQ[ks], &bF[0]);
                    mma16816h(S[2*ntp + 1], aQ[ks], &bF[2]);
                }
            }
        }

        const int kgl = ch * 128;
        float mt0 = -1e30f, mt1 = -1e30f;
        #pragma unroll
        for (int nt = 0; nt < 16; nt++) {
            float mkx = mks[kgl + nt*8 + 2*c4];
            float mky = mks[kgl + nt*8 + 2*c4 + 1];
            S[nt][0] += mkx;
            S[nt][1] += mky;
            S[nt][2] += mkx;
            S[nt][3] += mky;
            mt0 = fmaxf(mt0, fmaxf(S[nt][0], S[nt][1]));
            mt1 = fmaxf(mt1, fmaxf(S[nt][2], S[nt][3]));
        }
        mt0 = fmaxf(mt0, __shfl_xor_sync(0xffffffffu, mt0, 1));
        mt0 = fmaxf(mt0, __shfl_xor_sync(0xffffffffu, mt0, 2));
        mt1 = fmaxf(mt1, __shfl_xor_sync(0xffffffffu, mt1, 1));
        mt1 = fmaxf(mt1, __shfl_xor_sync(0xffffffffu, mt1, 2));

        float mn0 = fmaxf(m0, mt0), mn1 = fmaxf(m1, mt1);
        float al0 = exp2f(m0 - mn0), al1 = exp2f(m1 - mn1);
        #pragma unroll
        for (int nt = 0; nt < 8; nt++) {
            O[nt][0] *= al0; O[nt][1] *= al0;
            O[nt][2] *= al1; O[nt][3] *= al1;
        }

        uint32_t la0 = 0u, lb0 = 0u, la1 = 0u, lb1 = 0u;
        #pragma unroll
        for (int t = 0; t < 8; t++) {
            uint32_t P[4];
            P[0] = ex2h2(pkh(S[2*t][0]   - mn0, S[2*t][1]   - mn0));
            P[1] = ex2h2(pkh(S[2*t][2]   - mn1, S[2*t][3]   - mn1));
            P[2] = ex2h2(pkh(S[2*t+1][0] - mn0, S[2*t+1][1] - mn0));
            P[3] = ex2h2(pkh(S[2*t+1][2] - mn1, S[2*t+1][3] - mn1));
            uint32_t p02 = hadd2u(P[0], P[2]);
            uint32_t p13 = hadd2u(P[1], P[3]);
            if (t & 1) { lb0 = hadd2u(lb0, p02); lb1 = hadd2u(lb1, p13); }
            else       { la0 = hadd2u(la0, p02); la1 = hadd2u(la1, p13); }
            #pragma unroll
            for (int dp = 0; dp < 4; dp++) {
                uint32_t bF[4];
                ldsm4t(bF, vb + (t*16 + (vgrp & 1)*8 + vwi) * STRB + (dp*16 + (vgrp >> 1)*8) * 2);
                mma16816h(O[2*dp],     P, &bF[0]);
                mma16816h(O[2*dp + 1], P, &bF[2]);
            }
        }
        {
            float ls0 = h2sumf(hadd2u(la0, lb0));
            float ls1 = h2sumf(hadd2u(la1, lb1));
            ls0 += __shfl_xor_sync(0xffffffffu, ls0, 1);
            ls0 += __shfl_xor_sync(0xffffffffu, ls0, 2);
            ls1 += __shfl_xor_sync(0xffffffffu, ls1, 1);
            ls1 += __shfl_xor_sync(0xffffffffu, ls1, 2);
            l0 = l0 * al0 + ls0; m0 = mn0;
            l1 = l1 * al1 + ls1; m1 = mn1;
        }
        buf ^= 1;
    }

    // ---- staged epilogue: head-slice tile in SMEM -> coalesced global ----
    __syncthreads();                      // Q area dead; safe to overwrite
    __half* stg = (__half*)smc;           // [128][72] halves
    float i0 = 1.f / l0, i1 = 1.f / l1;
    #pragma unroll
    for (int nt = 0; nt < 8; nt++) {
        int cc = nt*8 + 2*c4;
        *(uint32_t*)(stg +  row0      * 72 + cc) = pkh(O[nt][0] * i0, O[nt][1] * i0);
        *(uint32_t*)(stg + (row0 + 8) * 72 + cc) = pkh(O[nt][2] * i1, O[nt][3] * i1);
    }
    __syncthreads();
    #pragma unroll
    for (int i = 0; i < 4; i++) {
        int idx = tid + i * 256;          // 1024 chunks of 8 halves (16B)
        int r = idx >> 3, ck = idx & 7;
        uint4 val = *(const uint4*)(stg + r * 72 + ck * 8);
        size_t o = (size_t)(b * TT + q0 + r) * HD + h * 64 + ck * 8;
        *(uint4*)(OutH + o) = val;
    }
}

// ---------------- layernorm ----------------
__device__ __forceinline__ float block_sum(float v, float* sh) {
    #pragma unroll
    for (int o = 16; o; o >>= 1) v += __shfl_xor_sync(0xffffffffu, v, o);
    int tid = threadIdx.x;
    if ((tid & 31) == 0) sh[tid >> 5] = v;
    __syncthreads();
    if (tid < 32) {
        float t = (tid < 8) ? sh[tid] : 0.f;
        #pragma unroll
        for (int o = 4; o; o >>= 1) t += __shfl_xor_sync(0xffffffffu, t, o);
        if (tid == 0) sh[0] = t;
    }
    __syncthreads();
    float r = sh[0];
    __syncthreads();
    return r;
}

__global__ __launch_bounds__(256) void ln_kernel(
    const float* __restrict__ Y,
    const float* __restrict__ g0, const float* __restrict__ b0,
    const float* __restrict__ g1, const float* __restrict__ b1,
    float* __restrict__ out)
{
    __shared__ float sh[8];
    int row = blockIdx.x, tid = threadIdx.x;
    const float* g  = (row < NB*TW) ? g0 : g1;
    const float* bt = (row < NB*TW) ? b0 : b1;
    float4 v = ((const float4*)(Y + (size_t)row * HD))[tid];
    float mu = block_sum(v.x + v.y + v.z + v.w, sh) * (1.f / HD);
    float4 d = make_float4(v.x - mu, v.y - mu, v.z - mu, v.w - mu);
    float var = block_sum(d.x*d.x + d.y*d.y + d.z*d.z + d.w*d.w, sh) * (1.f / HD);
    float rs = rsqrtf(var + 1e-12f);
    float4 gg = ((const float4*)g)[tid];
    float4 bb = ((const float4*)bt)[tid];
    ((float4*)(out + (size_t)row * HD))[tid] =
        make_float4(d.x*rs*gg.x + bb.x, d.y*rs*gg.y + bb.y, d.z*rs*gg.z + bb.z, d.w*rs*gg.w + bb.w);
}

// ---------------- launch ----------------
extern "C" void kernel_launch(void* const* d_in, const int* in_sizes, int n_in,
                              void* d_out, int out_size)
{
    (void)in_sizes; (void)n_in; (void)out_size;
    const float* word = (const float*)d_in[0];
    const float* ent  = (const float*)d_in[1];
    const float* mask = (const float*)d_in[2];
    const float* qpos = (const float*)d_in[3];
    const float* Wq  = (const float*)d_in[4];   const float* bq  = (const float*)d_in[5];
    const float* Wk  = (const float*)d_in[6];   const float* bk  = (const float*)d_in[7];
    const float* Wv  = (const float*)d_in[8];   const float* bv  = (const float*)d_in[9];
    const float* Weq = (const float*)d_in[10];  const float* beq = (const float*)d_in[11];
    const float* Wek = (const float*)d_in[12];  const float* bek = (const float*)d_in[13];
    const float* Wev = (const float*)d_in[14];  const float* bev = (const float*)d_in[15];
    const float* Wo  = (const float*)d_in[16];  const float* bo  = (const float*)d_in[17];
    const float* Weo = (const float*)d_in[18];  const float* beo = (const float*)d_in[19];
    const float* lng  = (const float*)d_in[20]; const float* lnb  = (const float*)d_in[21];
    const float* elng = (const float*)d_in[22]; const float* elnb = (const float*)d_in[23];
    float* out = (float*)d_out;

    float *Y;
    __half *QH, *KH, *VH, *Xh, *Wt;
    cudaGetSymbolAddress((void**)&Y,  g_Y);
    cudaGetSymbolAddress((void**)&QH, g_QH);
    cudaGetSymbolAddress((void**)&KH, g_KH);
    cudaGetSymbolAddress((void**)&VH, g_VH);
    cudaGetSymbolAddress((void**)&Xh, g_Xh);
    cudaGetSymbolAddress((void**)&Wt, g_Wt);

    cudaFuncSetAttribute(gemm_qkv, cudaFuncAttributeMaxDynamicSharedMemorySize, SMEM_QKV);
    cudaFuncSetAttribute(gemm_mma, cudaFuncAttributeMaxDynamicSharedMemorySize, SMEM_GEMM);
    cudaFuncSetAttribute(attn_tc,  cudaFuncAttributeMaxDynamicSharedMemorySize, ATTN_SMEM);

    // 1. unified prep
    PrepArgs pa;
    pa.w[0]=Wq; pa.w[1]=Wk; pa.w[2]=Wv; pa.w[3]=Weq; pa.w[4]=Wek; pa.w[5]=Wev; pa.w[6]=Wo; pa.w[7]=Weo;
    pa.word = word; pa.ent = ent; pa.qp = qpos;
    prep_kernel<<<dim3(1280, 1, 9), 256>>>(pa, Wt, Xh);

    // 2. QKV projections (128x256 fp16-acc, staged epilogue) -> fp16 head layout
    GemmCfg cq = {};
    cq.bias0[0]=bq;  cq.bias0[1]=bk;  cq.bias0[2]=bv;
    cq.bias1[0]=beq; cq.bias1[1]=bek; cq.bias1[2]=bev;
    cq.o[0]=QH; cq.o[1]=KH; cq.o[2]=VH;
    cq.widx0 = 0; cq.widx1 = 3; cq.ySplit = (NB*TW)/128;
    cq.Tseg0 = TW; cq.toffOut0 = 0;  cq.xb01_0 = 0;    cq.xb2_0 = 0;
    cq.Tseg1 = TE; cq.toffOut1 = TW; cq.xb01_1 = 4096; cq.xb2_1 = 4608;
    gemm_qkv<<<dim3(4, (NB*TW + NB*TE)/128, 3), 256, SMEM_QKV>>>(Xh, Wt, cq);

    // 3. attention (fp16, staged epilogue) -> CTX fp16 into Xh rows [0, 4608)
    attn_tc<<<dim3(TT/128, NB*NHD), 256, ATTN_SMEM>>>(QH, KH, VH, mask, Xh);

    // 4. output projections + residual -> unified Y
    GemmCfg co = {};
    co.bias0[0]=bo; co.bias1[0]=beo;
    co.o[0]=Y;
    co.res0 = word; co.res1 = ent;
    co.widx0 = 6; co.widx1 = 7; co.mode = 1; co.ySplit = (NB*TW)/128;
    co.Tseg0 = TW; co.Tfull0 = TT; co.toff0 = 0;
    co.Tseg1 = TE; co.Tfull1 = TT; co.toff1 = TW;
    co.outRowBase1 = NB*TW;
    gemm_mma<<<dim3(8, (NB*TW + NB*TE)/128, 1), 256, SMEM_GEMM>>>(Xh, Wt, co);

    // 5. layernorm -> d_out
    ln_kernel<<<NB*TW + NB*TE, 256>>>(Y, lng, lnb, elng, elnb, out);
}